// round 10
// baseline (speedup 1.0000x reference)
#include <cuda_runtime.h>
#include <cuda_bf16.h>
#include <math.h>

// Problem constants
#define BB   512
#define CC   128
#define TT   16
#define KK   20
#define C2   256
#define C4   512
#define CKK  2560   // K*C

// ---------------- scratch (static device globals; no allocation) ------------
__device__ float g_z   [BB * CC  * TT];
__device__ float g_y   [BB * CKK * TT];
__device__ float g_s1  [BB * C2  * TT];
__device__ float g_s2  [BB * C4  * TT];
__device__ float g_ql  [BB * CKK];
__device__ float g_mean [CKK];
__device__ float g_denom[CKK];

// ---------------- kernels ---------------------------------------------------

__global__ void zero_z_kernel(float* __restrict__ z) {
    int i = blockIdx.x * blockDim.x + threadIdx.x;
    if (i < BB * CC) z[i * TT] = 0.0f;
}

// GEMM: Y[b][m][l] = sum_c W[m][c] * IN[b][c][l]
// 128x128 tile, BK=8, 256 threads, 8x8 micro-tile, double-buffered smem.
// Bit-exact: each output element is ONE ascending-k FMA chain (Eigen gebp).
__global__ void __launch_bounds__(256, 2)
gemm128_kernel(const float* __restrict__ W,
               const float* __restrict__ inA,
               const float* __restrict__ inB,
               float* __restrict__ Y,
               int M, int Cin, int L, int mode)
{
    __shared__ float As[2][8][132];
    __shared__ float Bs[2][8][132];

    const int tid = threadIdx.x;
    const int n0 = blockIdx.x * 128;
    const int m0 = blockIdx.y * 128;

    // B loader: one column per thread, 4 k's (two k-subgroups across threads)
    const int bn  = tid & 127;
    const int bk4 = (tid >> 7) * 4;    // 0 or 4
    const int nB  = n0 + bn;
    const int nbL = nB / L;
    const int nlL = nB - nbL * L;

    // A loader: one float4 per thread
    const int arow = tid >> 1;          // 0..127
    const int akq  = (tid & 1) * 4;     // 0 or 4

    const int ty = tid >> 4;            // 0..15
    const int tx = tid & 15;            // 0..15

    const int KT = Cin >> 3;

    float acc[8][8] = {};
    float4 wv;
    float  bv[4];

    // ---- preload tile 0 ----
    wv = *(const float4*)&W[(size_t)(m0 + arow) * Cin + akq];
    As[0][akq + 0][arow] = wv.x;
    As[0][akq + 1][arow] = wv.y;
    As[0][akq + 2][arow] = wv.z;
    As[0][akq + 3][arow] = wv.w;
#pragma unroll
    for (int j = 0; j < 4; ++j) {
        int c = bk4 + j;
        float v;
        if (mode == 0) {
            const float* src = (c < CC) ? inA : inB;
            v = src[(((size_t)nbL << 7) + (c & (CC - 1))) * TT + nlL];
        } else {
            v = inA[((size_t)nbL * Cin + c) * TT + nlL];
        }
        Bs[0][bk4 + j][bn] = v;
    }
    __syncthreads();

    for (int kt = 0; kt < KT; ++kt) {
        const int cur = kt & 1;
        const bool more = (kt + 1 < KT);
        if (more) {
            const int k0 = (kt + 1) << 3;
            wv = *(const float4*)&W[(size_t)(m0 + arow) * Cin + k0 + akq];
#pragma unroll
            for (int j = 0; j < 4; ++j) {
                int c = k0 + bk4 + j;
                if (mode == 0) {
                    const float* src = (c < CC) ? inA : inB;
                    bv[j] = src[(((size_t)nbL << 7) + (c & (CC - 1))) * TT + nlL];
                } else {
                    bv[j] = inA[((size_t)nbL * Cin + c) * TT + nlL];
                }
            }
        }
#pragma unroll
        for (int k = 0; k < 8; ++k) {
            float a[8], b[8];
            *(float4*)&a[0] = *(const float4*)&As[cur][k][ty * 8];
            *(float4*)&a[4] = *(const float4*)&As[cur][k][ty * 8 + 4];
            *(float4*)&b[0] = *(const float4*)&Bs[cur][k][tx * 8];
            *(float4*)&b[4] = *(const float4*)&Bs[cur][k][tx * 8 + 4];
#pragma unroll
            for (int i = 0; i < 8; ++i)
#pragma unroll
                for (int j = 0; j < 8; ++j)
                    acc[i][j] = __fmaf_rn(a[i], b[j], acc[i][j]);
        }
        if (more) {
            const int nxt = cur ^ 1;
            As[nxt][akq + 0][arow] = wv.x;
            As[nxt][akq + 1][arow] = wv.y;
            As[nxt][akq + 2][arow] = wv.z;
            As[nxt][akq + 3][arow] = wv.w;
#pragma unroll
            for (int j = 0; j < 4; ++j)
                Bs[nxt][bk4 + j][bn] = bv[j];
            __syncthreads();
        }
    }

    // store
#pragma unroll
    for (int j = 0; j < 8; ++j) {
        int nn  = n0 + tx * 8 + j;
        int nbs = nn / L;
        int nls = nn - nbs * L;
        size_t base = ((size_t)nbs * M + m0 + ty * 8) * TT + nls;
#pragma unroll
        for (int i = 0; i < 8; ++i)
            Y[base + (size_t)i * TT] = acc[i][j];
    }
}

// ---- BN stats: frozen arithmetic (IC=2 over b; SLP row fold) ---------------

__device__ __forceinline__ void load_row(float* v, const float* row, int L)
{
    int j = 0;
    for (; j + 4 <= L; j += 4)
        *(float4*)&v[j] = *(const float4*)&row[j];
    for (; j < L; ++j)
        v[j] = row[j];
}

// Per-row horizontal sum (SLP shape) on a register array.
__device__ __forceinline__ float row_sum4(const float* v, int L)
{
    int W = (L >= 16) ? 16 : (L >= 8) ? 8 : 4;
    float h;
    if (W == 16) {
        float l[4];
#pragma unroll
        for (int j = 0; j < 4; ++j) {
            float a = __fadd_rn(v[j],     v[8 + j]);
            float b = __fadd_rn(v[4 + j], v[12 + j]);
            l[j] = __fadd_rn(a, b);
        }
        h = __fadd_rn(__fadd_rn(l[0], l[1]), __fadd_rn(l[2], l[3]));
    } else if (W == 8) {
        float u[4];
#pragma unroll
        for (int j = 0; j < 4; ++j)
            u[j] = __fadd_rn(v[j], v[4 + j]);
        h = __fadd_rn(__fadd_rn(u[0], u[1]), __fadd_rn(u[2], u[3]));
    } else {
        h = __fadd_rn(__fadd_rn(v[0], v[1]), __fadd_rn(v[2], v[3]));
    }
    for (int t = W; t < L; ++t)
        h = __fadd_rn(h, v[t]);
    return h;
}

__device__ __forceinline__ float fold_row(float s, const float* row, int L)
{
    float v[16];
    load_row(v, row, L);
    if (L < 4) {
        for (int t = 0; t < L; ++t) s = __fadd_rn(s, v[t]);
        return s;
    }
    return __fadd_rn(s, row_sum4(v, L));
}

__device__ __forceinline__ float fold_row_sq(float s, const float* row, int L, float m)
{
    float v[16], dd[16];
    load_row(v, row, L);
    for (int t = 0; t < L; ++t) {
        float d = __fsub_rn(v[t], m);
        dd[t] = __fmul_rn(d, d);
    }
    if (L < 4) {
        for (int t = 0; t < L; ++t) s = __fadd_rn(s, dd[t]);
        return s;
    }
    return __fadd_rn(s, row_sum4(dd, L));
}

__global__ void bnstats_kernel(const float* __restrict__ Y, int M, int L,
                               float* __restrict__ mean,
                               float* __restrict__ denom)
{
    int o = blockIdx.x * blockDim.x + threadIdx.x;
    if (o >= M) return;
    const float Nf = (float)(BB * L);

    float s0 = 0.0f, s1 = 0.0f;
#pragma unroll 2
    for (int b = 0; b < BB; b += 2) {
        s0 = fold_row(s0, Y + ((size_t)b       * M + o) * TT, L);
        s1 = fold_row(s1, Y + ((size_t)(b + 1) * M + o) * TT, L);
    }
    float s = __fadd_rn(s0, s1);
    float m = __fdiv_rn(s, Nf);

    float q0 = 0.0f, q1 = 0.0f;
#pragma unroll 2
    for (int b = 0; b < BB; b += 2) {
        q0 = fold_row_sq(q0, Y + ((size_t)b       * M + o) * TT, L, m);
        q1 = fold_row_sq(q1, Y + ((size_t)(b + 1) * M + o) * TT, L, m);
    }
    float q = __fadd_rn(q0, q1);
    float var = __fdiv_rn(q, Nf);

    mean[o]  = m;
    denom[o] = __fsqrt_rn(__fadd_rn(var, 1e-5f));
}

// Normalize + LIF; per-op rounding (frozen).
__global__ void lif_kernel(const float* __restrict__ Y,
                           const float* __restrict__ mean,
                           const float* __restrict__ denom,
                           const float* __restrict__ gamma,
                           const float* __restrict__ beta,
                           int M, int L,
                           float* __restrict__ out, int last_only)
{
    int idx = blockIdx.x * blockDim.x + threadIdx.x;
    if (idx >= BB * M) return;
    int ch = idx % M;
    float mn = mean[ch], dn = denom[ch], g = gamma[ch], be = beta[ch];
    const float* yp = Y + (size_t)idx * TT;
    float u = 0.f, o = 0.f;
    for (int l = 0; l < L; ++l) {
        float t0 = __fsub_rn(yp[l], mn);
        float t1 = __fmul_rn(0.4f, t0);
        float t2 = __fdiv_rn(t1, dn);
        float t3 = __fmul_rn(t2, g);
        float yn = __fadd_rn(t3, be);
        float a  = __fmul_rn(0.25f, u);
        float bq = __fmul_rn(a, __fsub_rn(1.0f, o));
        u = __fadd_rn(bq, yn);
        o = (u > 0.2f) ? 1.0f : 0.0f;
        if (!last_only) out[(size_t)idx * TT + l] = o;
    }
    if (last_only) out[idx] = o;
}

__global__ void gather_z_kernel(const float* __restrict__ ql,
                                const int* __restrict__ ridx,
                                float* __restrict__ z, int t)
{
    int i = blockIdx.x * blockDim.x + threadIdx.x;
    if (i >= BB * CC) return;
    int b = i >> 7, c = i & 127;
    int r = ridx[t * (BB * CC) + i];
    z[i * TT + (t + 1)] = ql[b * CKK + c * KK + r];
}

__global__ void gather_sampled_kernel(const float* __restrict__ qz,
                                      const int* __restrict__ ridx,
                                      float* __restrict__ sampled)
{
    int i = blockIdx.x * blockDim.x + threadIdx.x;
    if (i >= BB * CC * TT) return;
    int t  = i & 15;
    int bc = i >> 4;
    int b  = bc >> 7, c = bc & 127;
    int r  = ridx[t * (BB * CC) + bc];
    sampled[i] = qz[((size_t)b * CKK + c * KK + r) * TT + t];
}

// ---------------- host orchestration ---------------------------------------

static float* symf(const void* sym) {
    void* p = nullptr;
    cudaGetSymbolAddress(&p, sym);
    return (float*)p;
}

extern "C" void kernel_launch(void* const* d_in, const int* in_sizes, int n_in,
                              void* d_out, int out_size)
{
    const float* x    = (const float*)d_in[0];
    const int*   ridx = (const int*)  d_in[1];
    const float* W1   = (const float*)d_in[2];
    const float* g1   = (const float*)d_in[4];
    const float* be1  = (const float*)d_in[5];
    const float* W2   = (const float*)d_in[6];
    const float* g2   = (const float*)d_in[8];
    const float* be2  = (const float*)d_in[9];
    const float* W3   = (const float*)d_in[10];
    const float* g3   = (const float*)d_in[12];
    const float* be3  = (const float*)d_in[13];

    float* out     = (float*)d_out;
    float* sampled = out;
    float* qz      = out + (size_t)BB * CC * TT;

    float* zbuf  = symf(g_z);
    float* ybuf  = symf(g_y);
    float* s1    = symf(g_s1);
    float* s2    = symf(g_s2);
    float* ql    = symf(g_ql);
    float* meanb = symf(g_mean);
    float* denb  = symf(g_denom);

    zero_z_kernel<<<(BB * CC + 255) / 256, 256>>>(zbuf);

    for (int t = 0; t < TT - 1; ++t) {
        int L = t + 1;
        gemm128_kernel<<<dim3(4 * L, C2 / 128), 256>>>(W1, x, zbuf, ybuf, C2, C2, L, 0);
        bnstats_kernel<<<(C2 + 127) / 128, 128>>>(ybuf, C2, L, meanb, denb);
        lif_kernel<<<(BB * C2) / 256, 256>>>(ybuf, meanb, denb, g1, be1, C2, L, s1, 0);

        gemm128_kernel<<<dim3(4 * L, C4 / 128), 256>>>(W2, s1, nullptr, ybuf, C4, C2, L, 1);
        bnstats_kernel<<<(C4 + 127) / 128, 128>>>(ybuf, C4, L, meanb, denb);
        lif_kernel<<<(BB * C4) / 256, 256>>>(ybuf, meanb, denb, g2, be2, C4, L, s2, 0);

        gemm128_kernel<<<dim3(4 * L, CKK / 128), 256>>>(W3, s2, nullptr, ybuf, CKK, C4, L, 1);
        bnstats_kernel<<<(CKK + 127) / 128, 128>>>(ybuf, CKK, L, meanb, denb);
        lif_kernel<<<(BB * CKK) / 256, 256>>>(ybuf, meanb, denb, g3, be3, CKK, L, ql, 1);
        gather_z_kernel<<<(BB * CC + 255) / 256, 256>>>(ql, ridx, zbuf, t);
    }

    {
        int L = TT;
        gemm128_kernel<<<dim3(4 * L, C2 / 128), 256>>>(W1, x, zbuf, ybuf, C2, C2, L, 0);
        bnstats_kernel<<<(C2 + 127) / 128, 128>>>(ybuf, C2, L, meanb, denb);
        lif_kernel<<<(BB * C2) / 256, 256>>>(ybuf, meanb, denb, g1, be1, C2, L, s1, 0);

        gemm128_kernel<<<dim3(4 * L, C4 / 128), 256>>>(W2, s1, nullptr, ybuf, C4, C2, L, 1);
        bnstats_kernel<<<(C4 + 127) / 128, 128>>>(ybuf, C4, L, meanb, denb);
        lif_kernel<<<(BB * C4) / 256, 256>>>(ybuf, meanb, denb, g2, be2, C4, L, s2, 0);

        gemm128_kernel<<<dim3(4 * L, CKK / 128), 256>>>(W3, s2, nullptr, ybuf, CKK, C4, L, 1);
        bnstats_kernel<<<(CKK + 127) / 128, 128>>>(ybuf, CKK, L, meanb, denb);
        lif_kernel<<<(BB * CKK) / 256, 256>>>(ybuf, meanb, denb, g3, be3, CKK, L, qz, 0);
    }

    gather_sampled_kernel<<<(BB * CC * TT) / 256, 256>>>(qz, ridx, sampled);
}

// round 12
// speedup vs baseline: 1.1502x; 1.1502x over previous
#include <cuda_runtime.h>
#include <cuda_bf16.h>
#include <math.h>

// Problem constants
#define BB   512
#define CC   128
#define TT   16
#define KK   20
#define C2   256
#define C4   512
#define CKK  2560   // K*C

// ---------------- scratch (static device globals; no allocation) ------------
__device__ float g_z   [BB * CC  * TT];
__device__ float g_y   [BB * CKK * TT];
__device__ float g_s1  [BB * C2  * TT];
__device__ float g_s2  [BB * C4  * TT];
__device__ float g_ql  [BB * CKK];
__device__ float g_mean [CKK];
__device__ float g_denom[CKK];

// ---------------- kernels ---------------------------------------------------

__global__ void zero_z_kernel(float* __restrict__ z) {
    int i = blockIdx.x * blockDim.x + threadIdx.x;
    if (i < BB * CC) z[i * TT] = 0.0f;
}

__device__ __forceinline__ float ld_act(const float* __restrict__ inA,
                                        const float* __restrict__ inB,
                                        int mode, int Cin, int c, int nb, int nl)
{
    if (mode == 0) {
        const float* src = (c < CC) ? inA : inB;
        return src[(((size_t)nb << 7) + (c & (CC - 1))) * TT + nl];
    }
    return inA[((size_t)nb * Cin + c) * TT + nl];
}

// GEMM: Y[b][m][l] = sum_c W[m][c] * IN[b][c][l]
// 64x64 tile, BK=16, 256 threads, 4x4 micro-tile, DOUBLE-BUFFERED smem with
// register prefetch and ONE sync per k-tile.
// Bit-exact: each output element is ONE ascending-k FMA chain (Eigen gebp).
__global__ void gemm64_kernel(const float* __restrict__ W,
                              const float* __restrict__ inA,
                              const float* __restrict__ inB,
                              float* __restrict__ Y,
                              int M, int Cin, int L, int mode)
{
    __shared__ float As[2][16][68];
    __shared__ float Bs[2][16][68];

    const int tid = threadIdx.x;
    const int n0 = blockIdx.x * 64;
    const int m0 = blockIdx.y * 64;

    // B-tile loader mapping
    const int lk = tid >> 4;          // 0..15 (k row)
    const int ln = (tid & 15) * 4;    // n group (4 wide)
    int nb[4], nl[4];
#pragma unroll
    for (int j = 0; j < 4; ++j) {
        int n = n0 + ln + j;
        nb[j] = n / L;
        nl[j] = n - nb[j] * L;
    }
    // A-tile loader mapping
    const int lm  = tid >> 2;         // 0..63
    const int lk4 = (tid & 3) * 4;    // 0,4,8,12

    const int ty = tid >> 4;
    const int tx = tid & 15;

    const int KT = Cin >> 4;

    float acc[4][4] = {};
    float4 wv;
    float  bv[4];

    // ---- preload tile 0 ----
    wv = *(const float4*)&W[(size_t)(m0 + lm) * Cin + lk4];
    As[0][lk4 + 0][lm] = wv.x;
    As[0][lk4 + 1][lm] = wv.y;
    As[0][lk4 + 2][lm] = wv.z;
    As[0][lk4 + 3][lm] = wv.w;
#pragma unroll
    for (int j = 0; j < 4; ++j)
        Bs[0][lk][ln + j] = ld_act(inA, inB, mode, Cin, lk, nb[j], nl[j]);
    __syncthreads();

    for (int kt = 0; kt < KT; ++kt) {
        const int  cur  = kt & 1;
        const bool more = (kt + 1 < KT);
        if (more) {
            const int k0 = (kt + 1) << 4;
            wv = *(const float4*)&W[(size_t)(m0 + lm) * Cin + k0 + lk4];
#pragma unroll
            for (int j = 0; j < 4; ++j)
                bv[j] = ld_act(inA, inB, mode, Cin, k0 + lk, nb[j], nl[j]);
        }
#pragma unroll
        for (int k = 0; k < 16; ++k) {
            float4 a = *(const float4*)&As[cur][k][ty * 4];
            float4 b = *(const float4*)&Bs[cur][k][tx * 4];
            float av[4] = {a.x, a.y, a.z, a.w};
            float bw[4] = {b.x, b.y, b.z, b.w};
#pragma unroll
            for (int i = 0; i < 4; ++i)
#pragma unroll
                for (int j = 0; j < 4; ++j)
                    acc[i][j] = __fmaf_rn(av[i], bw[j], acc[i][j]);
        }
        if (more) {
            const int nxt = cur ^ 1;
            As[nxt][lk4 + 0][lm] = wv.x;
            As[nxt][lk4 + 1][lm] = wv.y;
            As[nxt][lk4 + 2][lm] = wv.z;
            As[nxt][lk4 + 3][lm] = wv.w;
#pragma unroll
            for (int j = 0; j < 4; ++j)
                Bs[nxt][lk][ln + j] = bv[j];
            __syncthreads();
        }
    }

    // store
#pragma unroll
    for (int j = 0; j < 4; ++j) {
        size_t base = ((size_t)nb[j] * M + m0 + ty * 4) * TT + nl[j];
#pragma unroll
        for (int i = 0; i < 4; ++i)
            Y[base + (size_t)i * TT] = acc[i][j];
    }
}

// ---- BN stats: EXACT R9 code (known-good, rel_err 0.0) ---------------------

// Per-row horizontal sum (LLVM SLP shape):
__device__ __forceinline__ float row_sum4(const float* v, int L)
{
    int W = (L >= 16) ? 16 : (L >= 8) ? 8 : 4;
    float h;
    if (W == 16) {
        float l[4];
#pragma unroll
        for (int j = 0; j < 4; ++j) {
            float a = __fadd_rn(v[j],     v[8 + j]);
            float b = __fadd_rn(v[4 + j], v[12 + j]);
            l[j] = __fadd_rn(a, b);
        }
        h = __fadd_rn(__fadd_rn(l[0], l[1]), __fadd_rn(l[2], l[3]));
    } else if (W == 8) {
        float u[4];
#pragma unroll
        for (int j = 0; j < 4; ++j)
            u[j] = __fadd_rn(v[j], v[4 + j]);
        h = __fadd_rn(__fadd_rn(u[0], u[1]), __fadd_rn(u[2], u[3]));
    } else {
        h = __fadd_rn(__fadd_rn(v[0], v[1]), __fadd_rn(v[2], v[3]));
    }
    for (int t = W; t < L; ++t)
        h = __fadd_rn(h, v[t]);
    return h;
}

__device__ __forceinline__ float fold_row(float s, const float* v, int L)
{
    if (L < 4) {
        for (int t = 0; t < L; ++t) s = __fadd_rn(s, v[t]);
        return s;
    }
    return __fadd_rn(s, row_sum4(v, L));
}

__device__ __forceinline__ float fold_row_sq(float s, const float* v, int L, float m)
{
    float dd[16];
    for (int t = 0; t < L; ++t) {
        float d = __fsub_rn(v[t], m);
        dd[t] = __fmul_rn(d, d);
    }
    return fold_row(s, dd, L);
}

// BN stats: LLVM LoopVectorizer INTERLEAVED reduction over b (IC=2).
__global__ void bnstats_kernel(const float* __restrict__ Y, int M, int L,
                               float* __restrict__ mean,
                               float* __restrict__ denom)
{
    int o = blockIdx.x * blockDim.x + threadIdx.x;
    if (o >= M) return;
    const float Nf = (float)(BB * L);

    float s0 = 0.0f, s1 = 0.0f;
    for (int b = 0; b < BB; b += 2) {
        s0 = fold_row(s0, Y + ((size_t)b       * M + o) * TT, L);
        s1 = fold_row(s1, Y + ((size_t)(b + 1) * M + o) * TT, L);
    }
    float s = __fadd_rn(s0, s1);
    float m = __fdiv_rn(s, Nf);

    float q0 = 0.0f, q1 = 0.0f;
    for (int b = 0; b < BB; b += 2) {
        q0 = fold_row_sq(q0, Y + ((size_t)b       * M + o) * TT, L, m);
        q1 = fold_row_sq(q1, Y + ((size_t)(b + 1) * M + o) * TT, L, m);
    }
    float q = __fadd_rn(q0, q1);
    float var = __fdiv_rn(q, Nf);

    mean[o]  = m;
    denom[o] = __fsqrt_rn(__fadd_rn(var, 1e-5f));
}

// Normalize + LIF; per-op rounding (frozen).
__global__ void lif_kernel(const float* __restrict__ Y,
                           const float* __restrict__ mean,
                           const float* __restrict__ denom,
                           const float* __restrict__ gamma,
                           const float* __restrict__ beta,
                           int M, int L,
                           float* __restrict__ out, int last_only)
{
    int idx = blockIdx.x * blockDim.x + threadIdx.x;
    if (idx >= BB * M) return;
    int ch = idx % M;
    float mn = mean[ch], dn = denom[ch], g = gamma[ch], be = beta[ch];
    const float* yp = Y + (size_t)idx * TT;
    float u = 0.f, o = 0.f;
    for (int l = 0; l < L; ++l) {
        float t0 = __fsub_rn(yp[l], mn);
        float t1 = __fmul_rn(0.4f, t0);
        float t2 = __fdiv_rn(t1, dn);
        float t3 = __fmul_rn(t2, g);
        float yn = __fadd_rn(t3, be);
        float a  = __fmul_rn(0.25f, u);
        float bq = __fmul_rn(a, __fsub_rn(1.0f, o));
        u = __fadd_rn(bq, yn);
        o = (u > 0.2f) ? 1.0f : 0.0f;
        if (!last_only) out[(size_t)idx * TT + l] = o;
    }
    if (last_only) out[idx] = o;
}

__global__ void gather_z_kernel(const float* __restrict__ ql,
                                const int* __restrict__ ridx,
                                float* __restrict__ z, int t)
{
    int i = blockIdx.x * blockDim.x + threadIdx.x;
    if (i >= BB * CC) return;
    int b = i >> 7, c = i & 127;
    int r = ridx[t * (BB * CC) + i];
    z[i * TT + (t + 1)] = ql[b * CKK + c * KK + r];
}

__global__ void gather_sampled_kernel(const float* __restrict__ qz,
                                      const int* __restrict__ ridx,
                                      float* __restrict__ sampled)
{
    int i = blockIdx.x * blockDim.x + threadIdx.x;
    if (i >= BB * CC * TT) return;
    int t  = i & 15;
    int bc = i >> 4;
    int b  = bc >> 7, c = bc & 127;
    int r  = ridx[t * (BB * CC) + bc];
    sampled[i] = qz[((size_t)b * CKK + c * KK + r) * TT + t];
}

// ---------------- host orchestration ---------------------------------------

static float* symf(const void* sym) {
    void* p = nullptr;
    cudaGetSymbolAddress(&p, sym);
    return (float*)p;
}

extern "C" void kernel_launch(void* const* d_in, const int* in_sizes, int n_in,
                              void* d_out, int out_size)
{
    const float* x    = (const float*)d_in[0];
    const int*   ridx = (const int*)  d_in[1];
    const float* W1   = (const float*)d_in[2];
    const float* g1   = (const float*)d_in[4];
    const float* be1  = (const float*)d_in[5];
    const float* W2   = (const float*)d_in[6];
    const float* g2   = (const float*)d_in[8];
    const float* be2  = (const float*)d_in[9];
    const float* W3   = (const float*)d_in[10];
    const float* g3   = (const float*)d_in[12];
    const float* be3  = (const float*)d_in[13];

    float* out     = (float*)d_out;
    float* sampled = out;
    float* qz      = out + (size_t)BB * CC * TT;

    float* zbuf  = symf(g_z);
    float* ybuf  = symf(g_y);
    float* s1    = symf(g_s1);
    float* s2    = symf(g_s2);
    float* ql    = symf(g_ql);
    float* meanb = symf(g_mean);
    float* denb  = symf(g_denom);

    zero_z_kernel<<<(BB * CC + 255) / 256, 256>>>(zbuf);

    for (int t = 0; t < TT - 1; ++t) {
        int L = t + 1;
        gemm64_kernel<<<dim3(8 * L, C2 / 64), 256>>>(W1, x, zbuf, ybuf, C2, C2, L, 0);
        bnstats_kernel<<<(C2 + 127) / 128, 128>>>(ybuf, C2, L, meanb, denb);
        lif_kernel<<<(BB * C2) / 256, 256>>>(ybuf, meanb, denb, g1, be1, C2, L, s1, 0);

        gemm64_kernel<<<dim3(8 * L, C4 / 64), 256>>>(W2, s1, nullptr, ybuf, C4, C2, L, 1);
        bnstats_kernel<<<(C4 + 127) / 128, 128>>>(ybuf, C4, L, meanb, denb);
        lif_kernel<<<(BB * C4) / 256, 256>>>(ybuf, meanb, denb, g2, be2, C4, L, s2, 0);

        gemm64_kernel<<<dim3(8 * L, CKK / 64), 256>>>(W3, s2, nullptr, ybuf, CKK, C4, L, 1);
        bnstats_kernel<<<(CKK + 127) / 128, 128>>>(ybuf, CKK, L, meanb, denb);
        lif_kernel<<<(BB * CKK) / 256, 256>>>(ybuf, meanb, denb, g3, be3, CKK, L, ql, 1);
        gather_z_kernel<<<(BB * CC + 255) / 256, 256>>>(ql, ridx, zbuf, t);
    }

    {
        int L = TT;
        gemm64_kernel<<<dim3(8 * L, C2 / 64), 256>>>(W1, x, zbuf, ybuf, C2, C2, L, 0);
        bnstats_kernel<<<(C2 + 127) / 128, 128>>>(ybuf, C2, L, meanb, denb);
        lif_kernel<<<(BB * C2) / 256, 256>>>(ybuf, meanb, denb, g1, be1, C2, L, s1, 0);

        gemm64_kernel<<<dim3(8 * L, C4 / 64), 256>>>(W2, s1, nullptr, ybuf, C4, C2, L, 1);
        bnstats_kernel<<<(C4 + 127) / 128, 128>>>(ybuf, C4, L, meanb, denb);
        lif_kernel<<<(BB * C4) / 256, 256>>>(ybuf, meanb, denb, g2, be2, C4, L, s2, 0);

        gemm64_kernel<<<dim3(8 * L, CKK / 64), 256>>>(W3, s2, nullptr, ybuf, CKK, C4, L, 1);
        bnstats_kernel<<<(CKK + 127) / 128, 128>>>(ybuf, CKK, L, meanb, denb);
        lif_kernel<<<(BB * CKK) / 256, 256>>>(ybuf, meanb, denb, g3, be3, CKK, L, qz, 0);
    }

    gather_sampled_kernel<<<(BB * CC * TT) / 256, 256>>>(qz, ridx, sampled);
}

// round 13
// speedup vs baseline: 1.1977x; 1.0413x over previous
#include <cuda_runtime.h>
#include <cuda_bf16.h>
#include <math.h>

// Problem constants
#define BB   512
#define CC   128
#define TT   16
#define KK   20
#define C2   256
#define C4   512
#define CKK  2560   // K*C

typedef unsigned long long ull;

// ---------------- scratch (static device globals; no allocation) ------------
__device__ float g_z   [BB * CC  * TT];
__device__ float g_y   [BB * CKK * TT];
__device__ float g_s1  [BB * C2  * TT];
__device__ float g_s2  [BB * C4  * TT];
__device__ float g_ql  [BB * CKK];
__device__ float g_mean [CKK];
__device__ float g_denom[CKK];
__device__ float g_diag[BB * CKK * TT];   // diagnostic GEMM output (unused)

// ---------------- kernels ---------------------------------------------------

__global__ void zero_z_kernel(float* __restrict__ z) {
    int i = blockIdx.x * blockDim.x + threadIdx.x;
    if (i < BB * CC) z[i * TT] = 0.0f;
}

__device__ __forceinline__ float ld_act(const float* __restrict__ inA,
                                        const float* __restrict__ inB,
                                        int mode, int Cin, int c, int nb, int nl)
{
    if (mode == 0) {
        const float* src = (c < CC) ? inA : inB;
        return src[(((size_t)nb << 7) + (c & (CC - 1))) * TT + nl];
    }
    return inA[((size_t)nb * Cin + c) * TT + nl];
}

__device__ __forceinline__ ull pack2(float x, float y) {
    ull r; asm("mov.b64 %0, {%1, %2};" : "=l"(r) : "f"(x), "f"(y)); return r;
}
__device__ __forceinline__ void unpack2(ull v, float& x, float& y) {
    asm("mov.b64 {%0, %1}, %2;" : "=f"(x), "=f"(y) : "l"(v));
}
// Packed dual fp32 FMA: two independent IEEE round-to-nearest FMAs (bit-exact
// per lane). SASS: FFMA2 (PTX-only path on sm_103a).
__device__ __forceinline__ ull fma2(ull a, ull b, ull c) {
    ull d;
    asm("fma.rn.f32x2 %0, %1, %2, %3;" : "=l"(d) : "l"(a), "l"(b), "l"(c));
    return d;
}

// GEMM: Y[b][m][l] = sum_c W[m][c] * IN[b][c][l]
// 128(m) x 64(n) tile, BK=16, 256 threads, 8x4 micro-tile via packed f32x2.
// Accumulators paired along m; each lane is one ascending-k FMA chain —
// bit-identical to the scalar Eigen-gebp chain.
__global__ void __launch_bounds__(256)
gemm128x64_kernel(const float* __restrict__ W,
                  const float* __restrict__ inA,
                  const float* __restrict__ inB,
                  float* __restrict__ Y,
                  int M, int Cin, int L, int mode)
{
    __shared__ float As[2][16][136];   // k-major, 128 rows + pad
    __shared__ float Bs[2][16][68];

    const int tid = threadIdx.x;
    const int n0 = blockIdx.x * 64;
    const int m0 = blockIdx.y * 128;

    // B-tile loader: 16 k-rows x 64 n
    const int lk = tid >> 4;
    const int ln = (tid & 15) * 4;
    int nb[4], nl[4];
#pragma unroll
    for (int j = 0; j < 4; ++j) {
        int n = n0 + ln + j;
        nb[j] = n / L;
        nl[j] = n - nb[j] * L;
    }
    // A-tile loader: 128 rows x 16 k; 2 float4 per thread
    const int arow = tid >> 1;
    const int akq  = (tid & 1) * 8;

    const int ty = tid >> 4;            // m-group: rows m0 + ty*8 .. +7
    const int tx = tid & 15;            // n-group: cols ln (== tx*4)

    const int KT = Cin >> 4;

    ull acc[4][4];                      // [m-pair][j]
#pragma unroll
    for (int i = 0; i < 4; ++i)
#pragma unroll
        for (int j = 0; j < 4; ++j) acc[i][j] = 0ull;

    float4 w0, w1;
    float  bv[4];

    // ---- preload tile 0 ----
    w0 = *(const float4*)&W[(size_t)(m0 + arow) * Cin + akq];
    w1 = *(const float4*)&W[(size_t)(m0 + arow) * Cin + akq + 4];
    As[0][akq + 0][arow] = w0.x;  As[0][akq + 1][arow] = w0.y;
    As[0][akq + 2][arow] = w0.z;  As[0][akq + 3][arow] = w0.w;
    As[0][akq + 4][arow] = w1.x;  As[0][akq + 5][arow] = w1.y;
    As[0][akq + 6][arow] = w1.z;  As[0][akq + 7][arow] = w1.w;
#pragma unroll
    for (int j = 0; j < 4; ++j)
        Bs[0][lk][ln + j] = ld_act(inA, inB, mode, Cin, lk, nb[j], nl[j]);
    __syncthreads();

    for (int kt = 0; kt < KT; ++kt) {
        const int  cur  = kt & 1;
        const bool more = (kt + 1 < KT);
        if (more) {
            const int k0 = (kt + 1) << 4;
            w0 = *(const float4*)&W[(size_t)(m0 + arow) * Cin + k0 + akq];
            w1 = *(const float4*)&W[(size_t)(m0 + arow) * Cin + k0 + akq + 4];
#pragma unroll
            for (int j = 0; j < 4; ++j)
                bv[j] = ld_act(inA, inB, mode, Cin, k0 + lk, nb[j], nl[j]);
        }
#pragma unroll
        for (int k = 0; k < 16; ++k) {
            float4 af0 = *(const float4*)&As[cur][k][ty * 8];
            float4 af1 = *(const float4*)&As[cur][k][ty * 8 + 4];
            float4 b4  = *(const float4*)&Bs[cur][k][tx * 4];
            ull ap[4];
            ap[0] = pack2(af0.x, af0.y);
            ap[1] = pack2(af0.z, af0.w);
            ap[2] = pack2(af1.x, af1.y);
            ap[3] = pack2(af1.z, af1.w);
            ull bd[4];
            bd[0] = pack2(b4.x, b4.x);
            bd[1] = pack2(b4.y, b4.y);
            bd[2] = pack2(b4.z, b4.z);
            bd[3] = pack2(b4.w, b4.w);
#pragma unroll
            for (int i = 0; i < 4; ++i)
#pragma unroll
                for (int j = 0; j < 4; ++j)
                    acc[i][j] = fma2(ap[i], bd[j], acc[i][j]);
        }
        if (more) {
            const int nxt = cur ^ 1;
            As[nxt][akq + 0][arow] = w0.x;  As[nxt][akq + 1][arow] = w0.y;
            As[nxt][akq + 2][arow] = w0.z;  As[nxt][akq + 3][arow] = w0.w;
            As[nxt][akq + 4][arow] = w1.x;  As[nxt][akq + 5][arow] = w1.y;
            As[nxt][akq + 6][arow] = w1.z;  As[nxt][akq + 7][arow] = w1.w;
#pragma unroll
            for (int j = 0; j < 4; ++j)
                Bs[nxt][lk][ln + j] = bv[j];
            __syncthreads();
        }
    }

    // store: m = m0 + ty*8 + 2*i (+0/1)
#pragma unroll
    for (int j = 0; j < 4; ++j) {
        size_t base = ((size_t)nb[j] * M + m0 + ty * 8) * TT + nl[j];
#pragma unroll
        for (int i = 0; i < 4; ++i) {
            float lo, hi;
            unpack2(acc[i][j], lo, hi);
            Y[base + (size_t)(2 * i + 0) * TT] = lo;
            Y[base + (size_t)(2 * i + 1) * TT] = hi;
        }
    }
}

// ---- BN stats: EXACT R9 per-thread code (frozen bits) ----------------------

__device__ __forceinline__ float row_sum4(const float* v, int L)
{
    int W = (L >= 16) ? 16 : (L >= 8) ? 8 : 4;
    float h;
    if (W == 16) {
        float l[4];
#pragma unroll
        for (int j = 0; j < 4; ++j) {
            float a = __fadd_rn(v[j],     v[8 + j]);
            float b = __fadd_rn(v[4 + j], v[12 + j]);
            l[j] = __fadd_rn(a, b);
        }
        h = __fadd_rn(__fadd_rn(l[0], l[1]), __fadd_rn(l[2], l[3]));
    } else if (W == 8) {
        float u[4];
#pragma unroll
        for (int j = 0; j < 4; ++j)
            u[j] = __fadd_rn(v[j], v[4 + j]);
        h = __fadd_rn(__fadd_rn(u[0], u[1]), __fadd_rn(u[2], u[3]));
    } else {
        h = __fadd_rn(__fadd_rn(v[0], v[1]), __fadd_rn(v[2], v[3]));
    }
    for (int t = W; t < L; ++t)
        h = __fadd_rn(h, v[t]);
    return h;
}

__device__ __forceinline__ float fold_row(float s, const float* v, int L)
{
    if (L < 4) {
        for (int t = 0; t < L; ++t) s = __fadd_rn(s, v[t]);
        return s;
    }
    return __fadd_rn(s, row_sum4(v, L));
}

__device__ __forceinline__ float fold_row_sq(float s, const float* v, int L, float m)
{
    float dd[16];
    for (int t = 0; t < L; ++t) {
        float d = __fsub_rn(v[t], m);
        dd[t] = __fmul_rn(d, d);
    }
    return fold_row(s, dd, L);
}

__global__ void bnstats_kernel(const float* __restrict__ Y, int M, int L,
                               float* __restrict__ mean,
                               float* __restrict__ denom)
{
    int o = blockIdx.x * blockDim.x + threadIdx.x;
    if (o >= M) return;
    const float Nf = (float)(BB * L);

    float s0 = 0.0f, s1 = 0.0f;
    for (int b = 0; b < BB; b += 2) {
        s0 = fold_row(s0, Y + ((size_t)b       * M + o) * TT, L);
        s1 = fold_row(s1, Y + ((size_t)(b + 1) * M + o) * TT, L);
    }
    float s = __fadd_rn(s0, s1);
    float m = __fdiv_rn(s, Nf);

    float q0 = 0.0f, q1 = 0.0f;
    for (int b = 0; b < BB; b += 2) {
        q0 = fold_row_sq(q0, Y + ((size_t)b       * M + o) * TT, L, m);
        q1 = fold_row_sq(q1, Y + ((size_t)(b + 1) * M + o) * TT, L, m);
    }
    float q = __fadd_rn(q0, q1);
    float var = __fdiv_rn(q, Nf);

    mean[o]  = m;
    denom[o] = __fsqrt_rn(__fadd_rn(var, 1e-5f));
}

// Normalize + LIF; per-op rounding (frozen).
__global__ void lif_kernel(const float* __restrict__ Y,
                           const float* __restrict__ mean,
                           const float* __restrict__ denom,
                           const float* __restrict__ gamma,
                           const float* __restrict__ beta,
                           int M, int L,
                           float* __restrict__ out, int last_only)
{
    int idx = blockIdx.x * blockDim.x + threadIdx.x;
    if (idx >= BB * M) return;
    int ch = idx % M;
    float mn = mean[ch], dn = denom[ch], g = gamma[ch], be = beta[ch];
    const float* yp = Y + (size_t)idx * TT;
    float u = 0.f, o = 0.f;
    for (int l = 0; l < L; ++l) {
        float t0 = __fsub_rn(yp[l], mn);
        float t1 = __fmul_rn(0.4f, t0);
        float t2 = __fdiv_rn(t1, dn);
        float t3 = __fmul_rn(t2, g);
        float yn = __fadd_rn(t3, be);
        float a  = __fmul_rn(0.25f, u);
        float bq = __fmul_rn(a, __fsub_rn(1.0f, o));
        u = __fadd_rn(bq, yn);
        o = (u > 0.2f) ? 1.0f : 0.0f;
        if (!last_only) out[(size_t)idx * TT + l] = o;
    }
    if (last_only) out[idx] = o;
}

__global__ void gather_z_kernel(const float* __restrict__ ql,
                                const int* __restrict__ ridx,
                                float* __restrict__ z, int t)
{
    int i = blockIdx.x * blockDim.x + threadIdx.x;
    if (i >= BB * CC) return;
    int b = i >> 7, c = i & 127;
    int r = ridx[t * (BB * CC) + i];
    z[i * TT + (t + 1)] = ql[b * CKK + c * KK + r];
}

__global__ void gather_sampled_kernel(const float* __restrict__ qz,
                                      const int* __restrict__ ridx,
                                      float* __restrict__ sampled)
{
    int i = blockIdx.x * blockDim.x + threadIdx.x;
    if (i >= BB * CC * TT) return;
    int t  = i & 15;
    int bc = i >> 4;
    int b  = bc >> 7, c = bc & 127;
    int r  = ridx[t * (BB * CC) + bc];
    sampled[i] = qz[((size_t)b * CKK + c * KK + r) * TT + t];
}

// ---------------- host orchestration ---------------------------------------

static float* symf(const void* sym) {
    void* p = nullptr;
    cudaGetSymbolAddress(&p, sym);
    return (float*)p;
}

extern "C" void kernel_launch(void* const* d_in, const int* in_sizes, int n_in,
                              void* d_out, int out_size)
{
    const float* x    = (const float*)d_in[0];
    const int*   ridx = (const int*)  d_in[1];
    const float* W1   = (const float*)d_in[2];
    const float* g1   = (const float*)d_in[4];
    const float* be1  = (const float*)d_in[5];
    const float* W2   = (const float*)d_in[6];
    const float* g2   = (const float*)d_in[8];
    const float* be2  = (const float*)d_in[9];
    const float* W3   = (const float*)d_in[10];
    const float* g3   = (const float*)d_in[12];
    const float* be3  = (const float*)d_in[13];

    float* out     = (float*)d_out;
    float* sampled = out;
    float* qz      = out + (size_t)BB * CC * TT;

    float* zbuf  = symf(g_z);
    float* ybuf  = symf(g_y);
    float* s1    = symf(g_s1);
    float* s2    = symf(g_s2);
    float* ql    = symf(g_ql);
    float* meanb = symf(g_mean);
    float* denb  = symf(g_denom);
    float* diag  = symf(g_diag);

    zero_z_kernel<<<(BB * CC + 255) / 256, 256>>>(zbuf);

    bool first = true;
    for (int t = 0; t < TT - 1; ++t) {
        int L = t + 1;
        gemm128x64_kernel<<<dim3(8 * L, C2 / 128), 256>>>(W1, x, zbuf, ybuf, C2, C2, L, 0);
        bnstats_kernel<<<(C2 + 31) / 32, 32>>>(ybuf, C2, L, meanb, denb);
        if (first) {
            // Diagnostic: full-scale layer-3 GEMM as our 4th launch so ncu
            // (-s 5 -c 1, after 2 harness launches) captures it. Output unused.
            gemm128x64_kernel<<<dim3(8 * TT, CKK / 128), 256>>>(W3, s2, nullptr, diag, CKK, C4, TT, 1);
            first = false;
        }
        lif_kernel<<<(BB * C2) / 256, 256>>>(ybuf, meanb, denb, g1, be1, C2, L, s1, 0);

        gemm128x64_kernel<<<dim3(8 * L, C4 / 128), 256>>>(W2, s1, nullptr, ybuf, C4, C2, L, 1);
        bnstats_kernel<<<(C4 + 31) / 32, 32>>>(ybuf, C4, L, meanb, denb);
        lif_kernel<<<(BB * C4) / 256, 256>>>(ybuf, meanb, denb, g2, be2, C4, L, s2, 0);

        gemm128x64_kernel<<<dim3(8 * L, CKK / 128), 256>>>(W3, s2, nullptr, ybuf, CKK, C4, L, 1);
        bnstats_kernel<<<(CKK + 31) / 32, 32>>>(ybuf, CKK, L, meanb, denb);
        lif_kernel<<<(BB * CKK) / 256, 256>>>(ybuf, meanb, denb, g3, be3, CKK, L, ql, 1);
        gather_z_kernel<<<(BB * CC + 255) / 256, 256>>>(ql, ridx, zbuf, t);
    }

    {
        int L = TT;
        gemm128x64_kernel<<<dim3(8 * L, C2 / 128), 256>>>(W1, x, zbuf, ybuf, C2, C2, L, 0);
        bnstats_kernel<<<(C2 + 31) / 32, 32>>>(ybuf, C2, L, meanb, denb);
        lif_kernel<<<(BB * C2) / 256, 256>>>(ybuf, meanb, denb, g1, be1, C2, L, s1, 0);

        gemm128x64_kernel<<<dim3(8 * L, C4 / 128), 256>>>(W2, s1, nullptr, ybuf, C4, C2, L, 1);
        bnstats_kernel<<<(C4 + 31) / 32, 32>>>(ybuf, C4, L, meanb, denb);
        lif_kernel<<<(BB * C4) / 256, 256>>>(ybuf, meanb, denb, g2, be2, C4, L, s2, 0);

        gemm128x64_kernel<<<dim3(8 * L, CKK / 128), 256>>>(W3, s2, nullptr, ybuf, CKK, C4, L, 1);
        bnstats_kernel<<<(CKK + 31) / 32, 32>>>(ybuf, CKK, L, meanb, denb);
        lif_kernel<<<(BB * CKK) / 256, 256>>>(ybuf, meanb, denb, g3, be3, CKK, L, qz, 0);
    }

    gather_sampled_kernel<<<(BB * CC * TT) / 256, 256>>>(qz, ridx, sampled);
}

// round 14
// speedup vs baseline: 5.1658x; 4.3130x over previous
#include <cuda_runtime.h>
#include <cuda_bf16.h>
#include <math.h>

// Problem constants
#define BB   512
#define CC   128
#define TT   16
#define KK   20
#define C2   256
#define C4   512
#define CKK  2560   // K*C

typedef unsigned long long ull;

// ---------------- scratch (static device globals; no allocation) ------------
__device__ float g_z   [BB * CC  * TT];
__device__ float g_y   [BB * CKK * TT];
__device__ float g_s1  [BB * C2  * TT];
__device__ float g_s2  [BB * C4  * TT];
__device__ float g_ql  [BB * CKK];
__device__ float g_mean [CKK];
__device__ float g_denom[CKK];
__device__ float g_dstat[2 * CKK];        // diagnostic bnstats output (unused)

// ---------------- kernels ---------------------------------------------------

__global__ void zero_z_kernel(float* __restrict__ z) {
    int i = blockIdx.x * blockDim.x + threadIdx.x;
    if (i < BB * CC) z[i * TT] = 0.0f;
}

__device__ __forceinline__ float ld_act(const float* __restrict__ inA,
                                        const float* __restrict__ inB,
                                        int mode, int Cin, int c, int nb, int nl)
{
    if (mode == 0) {
        const float* src = (c < CC) ? inA : inB;
        return src[(((size_t)nb << 7) + (c & (CC - 1))) * TT + nl];
    }
    return inA[((size_t)nb * Cin + c) * TT + nl];
}

__device__ __forceinline__ ull pack2(float x, float y) {
    ull r; asm("mov.b64 %0, {%1, %2};" : "=l"(r) : "f"(x), "f"(y)); return r;
}
__device__ __forceinline__ void unpack2(ull v, float& x, float& y) {
    asm("mov.b64 {%0, %1}, %2;" : "=f"(x), "=f"(y) : "l"(v));
}
// Packed dual fp32 FMA: two independent IEEE round-to-nearest FMAs (bit-exact
// per lane). SASS: FFMA2 (PTX-only path on sm_103a).
__device__ __forceinline__ ull fma2(ull a, ull b, ull c) {
    ull d;
    asm("fma.rn.f32x2 %0, %1, %2, %3;" : "=l"(d) : "l"(a), "l"(b), "l"(c));
    return d;
}

// GEMM: Y[b][m][l] = sum_c W[m][c] * IN[b][c][l]
// 128(m) x 64(n) tile, BK=16, 256 threads, 8x4 micro-tile via packed f32x2.
// Each lane is one ascending-k FMA chain — bit-identical to Eigen gebp.
__global__ void __launch_bounds__(256)
gemm128x64_kernel(const float* __restrict__ W,
                  const float* __restrict__ inA,
                  const float* __restrict__ inB,
                  float* __restrict__ Y,
                  int M, int Cin, int L, int mode)
{
    __shared__ float As[2][16][136];
    __shared__ float Bs[2][16][68];

    const int tid = threadIdx.x;
    const int n0 = blockIdx.x * 64;
    const int m0 = blockIdx.y * 128;

    const int lk = tid >> 4;
    const int ln = (tid & 15) * 4;
    int nb[4], nl[4];
#pragma unroll
    for (int j = 0; j < 4; ++j) {
        int n = n0 + ln + j;
        nb[j] = n / L;
        nl[j] = n - nb[j] * L;
    }
    const int arow = tid >> 1;
    const int akq  = (tid & 1) * 8;

    const int ty = tid >> 4;
    const int tx = tid & 15;

    const int KT = Cin >> 4;

    ull acc[4][4];
#pragma unroll
    for (int i = 0; i < 4; ++i)
#pragma unroll
        for (int j = 0; j < 4; ++j) acc[i][j] = 0ull;

    float4 w0, w1;
    float  bv[4];

    w0 = *(const float4*)&W[(size_t)(m0 + arow) * Cin + akq];
    w1 = *(const float4*)&W[(size_t)(m0 + arow) * Cin + akq + 4];
    As[0][akq + 0][arow] = w0.x;  As[0][akq + 1][arow] = w0.y;
    As[0][akq + 2][arow] = w0.z;  As[0][akq + 3][arow] = w0.w;
    As[0][akq + 4][arow] = w1.x;  As[0][akq + 5][arow] = w1.y;
    As[0][akq + 6][arow] = w1.z;  As[0][akq + 7][arow] = w1.w;
#pragma unroll
    for (int j = 0; j < 4; ++j)
        Bs[0][lk][ln + j] = ld_act(inA, inB, mode, Cin, lk, nb[j], nl[j]);
    __syncthreads();

    for (int kt = 0; kt < KT; ++kt) {
        const int  cur  = kt & 1;
        const bool more = (kt + 1 < KT);
        if (more) {
            const int k0 = (kt + 1) << 4;
            w0 = *(const float4*)&W[(size_t)(m0 + arow) * Cin + k0 + akq];
            w1 = *(const float4*)&W[(size_t)(m0 + arow) * Cin + k0 + akq + 4];
#pragma unroll
            for (int j = 0; j < 4; ++j)
                bv[j] = ld_act(inA, inB, mode, Cin, k0 + lk, nb[j], nl[j]);
        }
#pragma unroll
        for (int k = 0; k < 16; ++k) {
            float4 af0 = *(const float4*)&As[cur][k][ty * 8];
            float4 af1 = *(const float4*)&As[cur][k][ty * 8 + 4];
            float4 b4  = *(const float4*)&Bs[cur][k][tx * 4];
            ull ap[4];
            ap[0] = pack2(af0.x, af0.y);
            ap[1] = pack2(af0.z, af0.w);
            ap[2] = pack2(af1.x, af1.y);
            ap[3] = pack2(af1.z, af1.w);
            ull bd[4];
            bd[0] = pack2(b4.x, b4.x);
            bd[1] = pack2(b4.y, b4.y);
            bd[2] = pack2(b4.z, b4.z);
            bd[3] = pack2(b4.w, b4.w);
#pragma unroll
            for (int i = 0; i < 4; ++i)
#pragma unroll
                for (int j = 0; j < 4; ++j)
                    acc[i][j] = fma2(ap[i], bd[j], acc[i][j]);
        }
        if (more) {
            const int nxt = cur ^ 1;
            As[nxt][akq + 0][arow] = w0.x;  As[nxt][akq + 1][arow] = w0.y;
            As[nxt][akq + 2][arow] = w0.z;  As[nxt][akq + 3][arow] = w0.w;
            As[nxt][akq + 4][arow] = w1.x;  As[nxt][akq + 5][arow] = w1.y;
            As[nxt][akq + 6][arow] = w1.z;  As[nxt][akq + 7][arow] = w1.w;
#pragma unroll
            for (int j = 0; j < 4; ++j)
                Bs[nxt][lk][ln + j] = bv[j];
            __syncthreads();
        }
    }

#pragma unroll
    for (int j = 0; j < 4; ++j) {
        size_t base = ((size_t)nb[j] * M + m0 + ty * 8) * TT + nl[j];
#pragma unroll
        for (int i = 0; i < 4; ++i) {
            float lo, hi;
            unpack2(acc[i][j], lo, hi);
            Y[base + (size_t)(2 * i + 0) * TT] = lo;
            Y[base + (size_t)(2 * i + 1) * TT] = hi;
        }
    }
}

// ---- BN stats: parallel warp-per-channel, arithmetic FROZEN (R9 bits) ------

// Per-row horizontal sum — exact R9 row_sum4 shape, compile-time L.
template<int L>
__device__ __forceinline__ float row_sum4_t(const float* v)
{
    constexpr int W = (L >= 16) ? 16 : (L >= 8) ? 8 : 4;
    float h;
    if (W == 16) {
        float l[4];
#pragma unroll
        for (int j = 0; j < 4; ++j) {
            float a = __fadd_rn(v[j],     v[8 + j]);
            float b = __fadd_rn(v[4 + j], v[12 + j]);
            l[j] = __fadd_rn(a, b);
        }
        h = __fadd_rn(__fadd_rn(l[0], l[1]), __fadd_rn(l[2], l[3]));
    } else if (W == 8) {
        float u[4];
#pragma unroll
        for (int j = 0; j < 4; ++j)
            u[j] = __fadd_rn(v[j], v[4 + j]);
        h = __fadd_rn(__fadd_rn(u[0], u[1]), __fadd_rn(u[2], u[3]));
    } else {
        h = __fadd_rn(__fadd_rn(v[0], v[1]), __fadd_rn(v[2], v[3]));
    }
#pragma unroll
    for (int t = W; t < L; ++t)
        h = __fadd_rn(h, v[t]);
    return h;
}

// One warp per channel. Lanes compute the 512 per-row values in parallel
// (h_b for L>=4; raw staging for L<4); lanes 0/1 then run the EXACT serial
// IC=2 chains (s0 over even b, s1 over odd b) from shared memory.
// Values and rounding order identical to the R9 reference-matching kernel.
template<int L>
__global__ void bnstats_t(const float* __restrict__ Y, int M,
                          float* __restrict__ mean,
                          float* __restrict__ denom)
{
    constexpr int WPB  = (L < 4) ? 4 : 8;
    constexpr int PERW = (L < 4) ? (BB * L) : BB;
    __shared__ float sm[WPB * PERW];
    __shared__ float smb[WPB];

    const int wid  = threadIdx.x >> 5;
    const int lane = threadIdx.x & 31;
    const int o    = blockIdx.x * WPB + wid;
    const float Nf = (float)(BB * L);
    float* wsm = sm + wid * PERW;

    if (L >= 4) {
        // mean: parallel per-row horizontals
#pragma unroll
        for (int i = 0; i < BB / 32; ++i) {
            int b = i * 32 + lane;
            const float* row = Y + ((size_t)b * M + o) * TT;
            float v[L];
#pragma unroll
            for (int t = 0; t < L; ++t) v[t] = row[t];
            wsm[b] = row_sum4_t<L>(v);
        }
        __syncwarp();
        float sacc = 0.0f;
        if (lane < 2)
            for (int b = lane; b < BB; b += 2)
                sacc = __fadd_rn(sacc, wsm[b]);
        __syncwarp();
        float s1v = __shfl_sync(0xffffffffu, sacc, 1);
        if (lane == 0)
            smb[wid] = __fdiv_rn(__fadd_rn(sacc, s1v), Nf);
        __syncwarp();
        float m = smb[wid];

        // var: parallel per-row horizontals over dd
#pragma unroll
        for (int i = 0; i < BB / 32; ++i) {
            int b = i * 32 + lane;
            const float* row = Y + ((size_t)b * M + o) * TT;
            float dd[L];
#pragma unroll
            for (int t = 0; t < L; ++t) {
                float d = __fsub_rn(row[t], m);
                dd[t] = __fmul_rn(d, d);
            }
            wsm[b] = row_sum4_t<L>(dd);
        }
        __syncwarp();
        float qacc = 0.0f;
        if (lane < 2)
            for (int b = lane; b < BB; b += 2)
                qacc = __fadd_rn(qacc, wsm[b]);
        __syncwarp();
        float q1v = __shfl_sync(0xffffffffu, qacc, 1);
        if (lane == 0) {
            float var = __fdiv_rn(__fadd_rn(qacc, q1v), Nf);
            mean[o]  = m;
            denom[o] = __fsqrt_rn(__fadd_rn(var, 1e-5f));
        }
    } else {
        // stage raw rows
#pragma unroll
        for (int i = 0; i < BB / 32; ++i) {
            int b = i * 32 + lane;
            const float* row = Y + ((size_t)b * M + o) * TT;
#pragma unroll
            for (int t = 0; t < L; ++t)
                wsm[b * L + t] = row[t];
        }
        __syncwarp();
        float sacc = 0.0f;
        if (lane < 2)
            for (int b = lane; b < BB; b += 2)
#pragma unroll
                for (int t = 0; t < L; ++t)
                    sacc = __fadd_rn(sacc, wsm[b * L + t]);
        __syncwarp();
        float s1v = __shfl_sync(0xffffffffu, sacc, 1);
        if (lane == 0)
            smb[wid] = __fdiv_rn(__fadd_rn(sacc, s1v), Nf);
        __syncwarp();
        float m = smb[wid];

        float qacc = 0.0f;
        if (lane < 2)
            for (int b = lane; b < BB; b += 2)
#pragma unroll
                for (int t = 0; t < L; ++t) {
                    float d = __fsub_rn(wsm[b * L + t], m);
                    qacc = __fadd_rn(qacc, __fmul_rn(d, d));
                }
        __syncwarp();
        float q1v = __shfl_sync(0xffffffffu, qacc, 1);
        if (lane == 0) {
            float var = __fdiv_rn(__fadd_rn(qacc, q1v), Nf);
            mean[o]  = m;
            denom[o] = __fsqrt_rn(__fadd_rn(var, 1e-5f));
        }
    }
}

static void bnstats_launch(const float* Y, int M, int L,
                           float* mean, float* denom)
{
#define BN_CASE(LV) case LV: { \
        constexpr int WPB = (LV < 4) ? 4 : 8; \
        bnstats_t<LV><<<M / WPB, WPB * 32>>>(Y, M, mean, denom); } break;
    switch (L) {
        BN_CASE(1)  BN_CASE(2)  BN_CASE(3)  BN_CASE(4)
        BN_CASE(5)  BN_CASE(6)  BN_CASE(7)  BN_CASE(8)
        BN_CASE(9)  BN_CASE(10) BN_CASE(11) BN_CASE(12)
        BN_CASE(13) BN_CASE(14) BN_CASE(15) BN_CASE(16)
    }
#undef BN_CASE
}

// Normalize + LIF; per-op rounding (frozen).
__global__ void lif_kernel(const float* __restrict__ Y,
                           const float* __restrict__ mean,
                           const float* __restrict__ denom,
                           const float* __restrict__ gamma,
                           const float* __restrict__ beta,
                           int M, int L,
                           float* __restrict__ out, int last_only)
{
    int idx = blockIdx.x * blockDim.x + threadIdx.x;
    if (idx >= BB * M) return;
    int ch = idx % M;
    float mn = mean[ch], dn = denom[ch], g = gamma[ch], be = beta[ch];
    const float* yp = Y + (size_t)idx * TT;
    float u = 0.f, o = 0.f;
    for (int l = 0; l < L; ++l) {
        float t0 = __fsub_rn(yp[l], mn);
        float t1 = __fmul_rn(0.4f, t0);
        float t2 = __fdiv_rn(t1, dn);
        float t3 = __fmul_rn(t2, g);
        float yn = __fadd_rn(t3, be);
        float a  = __fmul_rn(0.25f, u);
        float bq = __fmul_rn(a, __fsub_rn(1.0f, o));
        u = __fadd_rn(bq, yn);
        o = (u > 0.2f) ? 1.0f : 0.0f;
        if (!last_only) out[(size_t)idx * TT + l] = o;
    }
    if (last_only) out[idx] = o;
}

__global__ void gather_z_kernel(const float* __restrict__ ql,
                                const int* __restrict__ ridx,
                                float* __restrict__ z, int t)
{
    int i = blockIdx.x * blockDim.x + threadIdx.x;
    if (i >= BB * CC) return;
    int b = i >> 7, c = i & 127;
    int r = ridx[t * (BB * CC) + i];
    z[i * TT + (t + 1)] = ql[b * CKK + c * KK + r];
}

__global__ void gather_sampled_kernel(const float* __restrict__ qz,
                                      const int* __restrict__ ridx,
                                      float* __restrict__ sampled)
{
    int i = blockIdx.x * blockDim.x + threadIdx.x;
    if (i >= BB * CC * TT) return;
    int t  = i & 15;
    int bc = i >> 4;
    int b  = bc >> 7, c = bc & 127;
    int r  = ridx[t * (BB * CC) + bc];
    sampled[i] = qz[((size_t)b * CKK + c * KK + r) * TT + t];
}

// ---------------- host orchestration ---------------------------------------

static float* symf(const void* sym) {
    void* p = nullptr;
    cudaGetSymbolAddress(&p, sym);
    return (float*)p;
}

extern "C" void kernel_launch(void* const* d_in, const int* in_sizes, int n_in,
                              void* d_out, int out_size)
{
    const float* x    = (const float*)d_in[0];
    const int*   ridx = (const int*)  d_in[1];
    const float* W1   = (const float*)d_in[2];
    const float* g1   = (const float*)d_in[4];
    const float* be1  = (const float*)d_in[5];
    const float* W2   = (const float*)d_in[6];
    const float* g2   = (const float*)d_in[8];
    const float* be2  = (const float*)d_in[9];
    const float* W3   = (const float*)d_in[10];
    const float* g3   = (const float*)d_in[12];
    const float* be3  = (const float*)d_in[13];

    float* out     = (float*)d_out;
    float* sampled = out;
    float* qz      = out + (size_t)BB * CC * TT;

    float* zbuf  = symf(g_z);
    float* ybuf  = symf(g_y);
    float* s1    = symf(g_s1);
    float* s2    = symf(g_s2);
    float* ql    = symf(g_ql);
    float* meanb = symf(g_mean);
    float* denb  = symf(g_denom);
    float* dstat = symf(g_dstat);

    zero_z_kernel<<<(BB * CC + 255) / 256, 256>>>(zbuf);

    bool first = true;
    for (int t = 0; t < TT - 1; ++t) {
        int L = t + 1;
        gemm128x64_kernel<<<dim3(8 * L, C2 / 128), 256>>>(W1, x, zbuf, ybuf, C2, C2, L, 0);
        bnstats_launch(ybuf, C2, L, meanb, denb);
        if (first) {
            // Diagnostic: full-scale layer-3 bnstats as an early launch so the
            // ncu single-launch capture lands on it. Output unused/deterministic.
            bnstats_launch(ybuf, CKK, TT, dstat, dstat + CKK);
            first = false;
        }
        lif_kernel<<<(BB * C2) / 256, 256>>>(ybuf, meanb, denb, g1, be1, C2, L, s1, 0);

        gemm128x64_kernel<<<dim3(8 * L, C4 / 128), 256>>>(W2, s1, nullptr, ybuf, C4, C2, L, 1);
        bnstats_launch(ybuf, C4, L, meanb, denb);
        lif_kernel<<<(BB * C4) / 256, 256>>>(ybuf, meanb, denb, g2, be2, C4, L, s2, 0);

        gemm128x64_kernel<<<dim3(8 * L, CKK / 128), 256>>>(W3, s2, nullptr, ybuf, CKK, C4, L, 1);
        bnstats_launch(ybuf, CKK, L, meanb, denb);
        lif_kernel<<<(BB * CKK) / 256, 256>>>(ybuf, meanb, denb, g3, be3, CKK, L, ql, 1);
        gather_z_kernel<<<(BB * CC + 255) / 256, 256>>>(ql, ridx, zbuf, t);
    }

    {
        int L = TT;
        gemm128x64_kernel<<<dim3(8 * L, C2 / 128), 256>>>(W1, x, zbuf, ybuf, C2, C2, L, 0);
        bnstats_launch(ybuf, C2, L, meanb, denb);
        lif_kernel<<<(BB * C2) / 256, 256>>>(ybuf, meanb, denb, g1, be1, C2, L, s1, 0);

        gemm128x64_kernel<<<dim3(8 * L, C4 / 128), 256>>>(W2, s1, nullptr, ybuf, C4, C2, L, 1);
        bnstats_launch(ybuf, C4, L, meanb, denb);
        lif_kernel<<<(BB * C4) / 256, 256>>>(ybuf, meanb, denb, g2, be2, C4, L, s2, 0);

        gemm128x64_kernel<<<dim3(8 * L, CKK / 128), 256>>>(W3, s2, nullptr, ybuf, CKK, C4, L, 1);
        bnstats_launch(ybuf, CKK, L, meanb, denb);
        lif_kernel<<<(BB * CKK) / 256, 256>>>(ybuf, meanb, denb, g3, be3, CKK, L, qz, 0);
    }

    gather_sampled_kernel<<<(BB * CC * TT) / 256, 256>>>(qz, ridx, sampled);
}

// round 15
// speedup vs baseline: 5.5094x; 1.0665x over previous
#include <cuda_runtime.h>
#include <cuda_bf16.h>
#include <math.h>

// Problem constants
#define BB   512
#define CC   128
#define TT   16
#define KK   20
#define C2   256
#define C4   512
#define CKK  2560   // K*C

typedef unsigned long long ull;

// ---------------- scratch (static device globals; no allocation) ------------
__device__ float g_z   [BB * CC  * TT];
__device__ float g_y   [BB * CKK * TT];
__device__ float g_s1  [BB * C2  * TT];
__device__ float g_s2  [BB * C4  * TT];
__device__ float g_ql  [BB * CKK];
__device__ float g_mean [CKK];
__device__ float g_denom[CKK];
__device__ float g_dstat[2 * CKK];        // diagnostic bnstats output (unused)

// ---------------- kernels ---------------------------------------------------

__global__ void zero_z_kernel(float* __restrict__ z) {
    int i = blockIdx.x * blockDim.x + threadIdx.x;
    if (i < BB * CC) z[i * TT] = 0.0f;
}

__device__ __forceinline__ float ld_act(const float* __restrict__ inA,
                                        const float* __restrict__ inB,
                                        int mode, int Cin, int c, int nb, int nl)
{
    if (mode == 0) {
        const float* src = (c < CC) ? inA : inB;
        return src[(((size_t)nb << 7) + (c & (CC - 1))) * TT + nl];
    }
    return inA[((size_t)nb * Cin + c) * TT + nl];
}

__device__ __forceinline__ ull pack2(float x, float y) {
    ull r; asm("mov.b64 %0, {%1, %2};" : "=l"(r) : "f"(x), "f"(y)); return r;
}
__device__ __forceinline__ void unpack2(ull v, float& x, float& y) {
    asm("mov.b64 {%0, %1}, %2;" : "=f"(x), "=f"(y) : "l"(v));
}
// Packed dual fp32 FMA: two independent IEEE round-to-nearest FMAs (bit-exact
// per lane). SASS: FFMA2 (PTX-only path on sm_103a).
__device__ __forceinline__ ull fma2(ull a, ull b, ull c) {
    ull d;
    asm("fma.rn.f32x2 %0, %1, %2, %3;" : "=l"(d) : "l"(a), "l"(b), "l"(c));
    return d;
}

// GEMM: Y[b][m][l] = sum_c W[m][c] * IN[b][c][l]
// 128(m) x 64(n) tile, BK=16, 256 threads, 8x4 micro-tile via packed f32x2.
// Each lane is one ascending-k FMA chain — bit-identical to Eigen gebp.
__global__ void __launch_bounds__(256, 3)
gemm128x64_kernel(const float* __restrict__ W,
                  const float* __restrict__ inA,
                  const float* __restrict__ inB,
                  float* __restrict__ Y,
                  int M, int Cin, int L, int mode)
{
    __shared__ float As[2][16][136];
    __shared__ float Bs[2][16][68];

    const int tid = threadIdx.x;
    const int n0 = blockIdx.x * 64;
    const int m0 = blockIdx.y * 128;

    const int lk = tid >> 4;
    const int ln = (tid & 15) * 4;
    int nb[4], nl[4];
#pragma unroll
    for (int j = 0; j < 4; ++j) {
        int n = n0 + ln + j;
        nb[j] = n / L;
        nl[j] = n - nb[j] * L;
    }
    const int arow = tid >> 1;
    const int akq  = (tid & 1) * 8;

    const int ty = tid >> 4;
    const int tx = tid & 15;

    const int KT = Cin >> 4;

    ull acc[4][4];
#pragma unroll
    for (int i = 0; i < 4; ++i)
#pragma unroll
        for (int j = 0; j < 4; ++j) acc[i][j] = 0ull;

    float4 w0, w1;
    float  bv[4];

    w0 = *(const float4*)&W[(size_t)(m0 + arow) * Cin + akq];
    w1 = *(const float4*)&W[(size_t)(m0 + arow) * Cin + akq + 4];
    As[0][akq + 0][arow] = w0.x;  As[0][akq + 1][arow] = w0.y;
    As[0][akq + 2][arow] = w0.z;  As[0][akq + 3][arow] = w0.w;
    As[0][akq + 4][arow] = w1.x;  As[0][akq + 5][arow] = w1.y;
    As[0][akq + 6][arow] = w1.z;  As[0][akq + 7][arow] = w1.w;
#pragma unroll
    for (int j = 0; j < 4; ++j)
        Bs[0][lk][ln + j] = ld_act(inA, inB, mode, Cin, lk, nb[j], nl[j]);
    __syncthreads();

    for (int kt = 0; kt < KT; ++kt) {
        const int  cur  = kt & 1;
        const bool more = (kt + 1 < KT);
        if (more) {
            const int k0 = (kt + 1) << 4;
            w0 = *(const float4*)&W[(size_t)(m0 + arow) * Cin + k0 + akq];
            w1 = *(const float4*)&W[(size_t)(m0 + arow) * Cin + k0 + akq + 4];
#pragma unroll
            for (int j = 0; j < 4; ++j)
                bv[j] = ld_act(inA, inB, mode, Cin, k0 + lk, nb[j], nl[j]);
        }
#pragma unroll
        for (int k = 0; k < 16; ++k) {
            float4 af0 = *(const float4*)&As[cur][k][ty * 8];
            float4 af1 = *(const float4*)&As[cur][k][ty * 8 + 4];
            float4 b4  = *(const float4*)&Bs[cur][k][tx * 4];
            ull ap[4];
            ap[0] = pack2(af0.x, af0.y);
            ap[1] = pack2(af0.z, af0.w);
            ap[2] = pack2(af1.x, af1.y);
            ap[3] = pack2(af1.z, af1.w);
            ull bd[4];
            bd[0] = pack2(b4.x, b4.x);
            bd[1] = pack2(b4.y, b4.y);
            bd[2] = pack2(b4.z, b4.z);
            bd[3] = pack2(b4.w, b4.w);
#pragma unroll
            for (int i = 0; i < 4; ++i)
#pragma unroll
                for (int j = 0; j < 4; ++j)
                    acc[i][j] = fma2(ap[i], bd[j], acc[i][j]);
        }
        if (more) {
            const int nxt = cur ^ 1;
            As[nxt][akq + 0][arow] = w0.x;  As[nxt][akq + 1][arow] = w0.y;
            As[nxt][akq + 2][arow] = w0.z;  As[nxt][akq + 3][arow] = w0.w;
            As[nxt][akq + 4][arow] = w1.x;  As[nxt][akq + 5][arow] = w1.y;
            As[nxt][akq + 6][arow] = w1.z;  As[nxt][akq + 7][arow] = w1.w;
#pragma unroll
            for (int j = 0; j < 4; ++j)
                Bs[nxt][lk][ln + j] = bv[j];
            __syncthreads();
        }
    }

#pragma unroll
    for (int j = 0; j < 4; ++j) {
        size_t base = ((size_t)nb[j] * M + m0 + ty * 8) * TT + nl[j];
#pragma unroll
        for (int i = 0; i < 4; ++i) {
            float lo, hi;
            unpack2(acc[i][j], lo, hi);
            Y[base + (size_t)(2 * i + 0) * TT] = lo;
            Y[base + (size_t)(2 * i + 1) * TT] = hi;
        }
    }
}

// ---- BN stats: arithmetic FROZEN (R9 bits) ----------------------------------

// Per-row horizontal sum — exact R9 row_sum4 shape, compile-time L (L>=4).
template<int L>
__device__ __forceinline__ float row_sum4_t(const float* v)
{
    constexpr int W = (L >= 16) ? 16 : (L >= 8) ? 8 : 4;
    float h;
    if (W == 16) {
        float l[4];
#pragma unroll
        for (int j = 0; j < 4; ++j) {
            float a = __fadd_rn(v[j],     v[8 + j]);
            float b = __fadd_rn(v[4 + j], v[12 + j]);
            l[j] = __fadd_rn(a, b);
        }
        h = __fadd_rn(__fadd_rn(l[0], l[1]), __fadd_rn(l[2], l[3]));
    } else if (W == 8) {
        float u[4];
#pragma unroll
        for (int j = 0; j < 4; ++j)
            u[j] = __fadd_rn(v[j], v[4 + j]);
        h = __fadd_rn(__fadd_rn(u[0], u[1]), __fadd_rn(u[2], u[3]));
    } else {
        h = __fadd_rn(__fadd_rn(v[0], v[1]), __fadd_rn(v[2], v[3]));
    }
#pragma unroll
    for (int t = W; t < L; ++t)
        h = __fadd_rn(h, v[t]);
    return h;
}

// Coalesced bnstats for L>=4. Block = 256 threads = 8 warps = 8 channels.
// Rows staged to smem in 64-b chunks with contiguous 512B warp loads
// (channels o0..o0+7 are adjacent in memory). Warp w computes the EXACT
// row_sum4 horizontals for channel o0+w; lanes 0/1 extend the EXACT serial
// IC=2 chains in ascending-b order. Bit-identical to R9.
template<int L>
__global__ void __launch_bounds__(256)
bnstats_coal(const float* __restrict__ Y, int M,
             float* __restrict__ mean, float* __restrict__ denom)
{
    constexpr int CH  = 8;
    constexpr int BCH = 64;              // b rows per staging chunk
    constexpr int NCH = BB / BCH;        // 8 chunks
    constexpr int RS  = CH * TT + 4;     // 132-float row stride (16B aligned)
    __shared__ float st[BCH * RS];       // ~33 KB
    __shared__ float hb[CH * BCH];       // 2 KB
    __shared__ float smm[CH];

    const int tid  = threadIdx.x;
    const int w    = tid >> 5;
    const int lane = tid & 31;
    const int o0   = blockIdx.x * CH;
    const float Nf = (float)(BB * L);

    // ---- mean pass ----
    float sch = 0.0f;
    for (int c = 0; c < NCH; ++c) {
        int b0 = c * BCH;
#pragma unroll
        for (int i = 0; i < BCH / 8; ++i) {
            int bl = i * 8 + w;
            const float4* src = (const float4*)(Y + ((size_t)(b0 + bl) * M + o0) * TT);
            *(float4*)&st[bl * RS + lane * 4] = src[lane];
        }
        __syncthreads();
#pragma unroll
        for (int half = 0; half < BCH / 32; ++half) {
            int bl = half * 32 + lane;
            float v[L];
#pragma unroll
            for (int t = 0; t < L; ++t) v[t] = st[bl * RS + w * TT + t];
            hb[w * BCH + bl] = row_sum4_t<L>(v);
        }
        __syncwarp();
        if (lane < 2)
            for (int bl = lane; bl < BCH; bl += 2)
                sch = __fadd_rn(sch, hb[w * BCH + bl]);
        __syncthreads();
    }
    {
        float s1v = __shfl_sync(0xffffffffu, sch, 1);
        if (lane == 0)
            smm[w] = __fdiv_rn(__fadd_rn(sch, s1v), Nf);
    }
    __syncwarp();
    const float m = smm[w];

    // ---- var pass (same tree over dd) ----
    float qch = 0.0f;
    for (int c = 0; c < NCH; ++c) {
        int b0 = c * BCH;
#pragma unroll
        for (int i = 0; i < BCH / 8; ++i) {
            int bl = i * 8 + w;
            const float4* src = (const float4*)(Y + ((size_t)(b0 + bl) * M + o0) * TT);
            *(float4*)&st[bl * RS + lane * 4] = src[lane];
        }
        __syncthreads();
#pragma unroll
        for (int half = 0; half < BCH / 32; ++half) {
            int bl = half * 32 + lane;
            float dd[L];
#pragma unroll
            for (int t = 0; t < L; ++t) {
                float d = __fsub_rn(st[bl * RS + w * TT + t], m);
                dd[t] = __fmul_rn(d, d);
            }
            hb[w * BCH + bl] = row_sum4_t<L>(dd);
        }
        __syncwarp();
        if (lane < 2)
            for (int bl = lane; bl < BCH; bl += 2)
                qch = __fadd_rn(qch, hb[w * BCH + bl]);
        __syncthreads();
    }
    {
        float q1v = __shfl_sync(0xffffffffu, qch, 1);
        if (lane == 0) {
            float var = __fdiv_rn(__fadd_rn(qch, q1v), Nf);
            mean[o0 + w]  = m;
            denom[o0 + w] = __fsqrt_rn(__fadd_rn(var, 1e-5f));
        }
    }
}

// Small-L bnstats (L<4): proven R14 kernel (elementwise serial chains from smem).
template<int L>
__global__ void bnstats_small(const float* __restrict__ Y, int M,
                              float* __restrict__ mean,
                              float* __restrict__ denom)
{
    constexpr int WPB  = 4;
    constexpr int PERW = BB * L;
    __shared__ float sm[WPB * PERW];
    __shared__ float smb[WPB];

    const int wid  = threadIdx.x >> 5;
    const int lane = threadIdx.x & 31;
    const int o    = blockIdx.x * WPB + wid;
    const float Nf = (float)(BB * L);
    float* wsm = sm + wid * PERW;

#pragma unroll
    for (int i = 0; i < BB / 32; ++i) {
        int b = i * 32 + lane;
        const float* row = Y + ((size_t)b * M + o) * TT;
#pragma unroll
        for (int t = 0; t < L; ++t)
            wsm[b * L + t] = row[t];
    }
    __syncwarp();
    float sacc = 0.0f;
    if (lane < 2)
        for (int b = lane; b < BB; b += 2)
#pragma unroll
            for (int t = 0; t < L; ++t)
                sacc = __fadd_rn(sacc, wsm[b * L + t]);
    __syncwarp();
    float s1v = __shfl_sync(0xffffffffu, sacc, 1);
    if (lane == 0)
        smb[wid] = __fdiv_rn(__fadd_rn(sacc, s1v), Nf);
    __syncwarp();
    float m = smb[wid];

    float qacc = 0.0f;
    if (lane < 2)
        for (int b = lane; b < BB; b += 2)
#pragma unroll
            for (int t = 0; t < L; ++t) {
                float d = __fsub_rn(wsm[b * L + t], m);
                qacc = __fadd_rn(qacc, __fmul_rn(d, d));
            }
    __syncwarp();
    float q1v = __shfl_sync(0xffffffffu, qacc, 1);
    if (lane == 0) {
        float var = __fdiv_rn(__fadd_rn(qacc, q1v), Nf);
        mean[o]  = m;
        denom[o] = __fsqrt_rn(__fadd_rn(var, 1e-5f));
    }
}

static void bnstats_launch(const float* Y, int M, int L,
                           float* mean, float* denom)
{
#define BN_SMALL(LV) case LV: bnstats_small<LV><<<M / 4, 128>>>(Y, M, mean, denom); break;
#define BN_COAL(LV)  case LV: bnstats_coal<LV><<<M / 8, 256>>>(Y, M, mean, denom); break;
    switch (L) {
        BN_SMALL(1) BN_SMALL(2) BN_SMALL(3)
        BN_COAL(4)  BN_COAL(5)  BN_COAL(6)  BN_COAL(7)
        BN_COAL(8)  BN_COAL(9)  BN_COAL(10) BN_COAL(11)
        BN_COAL(12) BN_COAL(13) BN_COAL(14) BN_COAL(15) BN_COAL(16)
    }
#undef BN_SMALL
#undef BN_COAL
}

// Normalize + LIF; per-op rounding (frozen).
__global__ void lif_kernel(const float* __restrict__ Y,
                           const float* __restrict__ mean,
                           const float* __restrict__ denom,
                           const float* __restrict__ gamma,
                           const float* __restrict__ beta,
                           int M, int L,
                           float* __restrict__ out, int last_only)
{
    int idx = blockIdx.x * blockDim.x + threadIdx.x;
    if (idx >= BB * M) return;
    int ch = idx % M;
    float mn = mean[ch], dn = denom[ch], g = gamma[ch], be = beta[ch];
    const float* yp = Y + (size_t)idx * TT;
    float u = 0.f, o = 0.f;
    for (int l = 0; l < L; ++l) {
        float t0 = __fsub_rn(yp[l], mn);
        float t1 = __fmul_rn(0.4f, t0);
        float t2 = __fdiv_rn(t1, dn);
        float t3 = __fmul_rn(t2, g);
        float yn = __fadd_rn(t3, be);
        float a  = __fmul_rn(0.25f, u);
        float bq = __fmul_rn(a, __fsub_rn(1.0f, o));
        u = __fadd_rn(bq, yn);
        o = (u > 0.2f) ? 1.0f : 0.0f;
        if (!last_only) out[(size_t)idx * TT + l] = o;
    }
    if (last_only) out[idx] = o;
}

__global__ void gather_z_kernel(const float* __restrict__ ql,
                                const int* __restrict__ ridx,
                                float* __restrict__ z, int t)
{
    int i = blockIdx.x * blockDim.x + threadIdx.x;
    if (i >= BB * CC) return;
    int b = i >> 7, c = i & 127;
    int r = ridx[t * (BB * CC) + i];
    z[i * TT + (t + 1)] = ql[b * CKK + c * KK + r];
}

__global__ void gather_sampled_kernel(const float* __restrict__ qz,
                                      const int* __restrict__ ridx,
                                      float* __restrict__ sampled)
{
    int i = blockIdx.x * blockDim.x + threadIdx.x;
    if (i >= BB * CC * TT) return;
    int t  = i & 15;
    int bc = i >> 4;
    int b  = bc >> 7, c = bc & 127;
    int r  = ridx[t * (BB * CC) + bc];
    sampled[i] = qz[((size_t)b * CKK + c * KK + r) * TT + t];
}

// ---------------- host orchestration ---------------------------------------

static float* symf(const void* sym) {
    void* p = nullptr;
    cudaGetSymbolAddress(&p, sym);
    return (float*)p;
}

extern "C" void kernel_launch(void* const* d_in, const int* in_sizes, int n_in,
                              void* d_out, int out_size)
{
    const float* x    = (const float*)d_in[0];
    const int*   ridx = (const int*)  d_in[1];
    const float* W1   = (const float*)d_in[2];
    const float* g1   = (const float*)d_in[4];
    const float* be1  = (const float*)d_in[5];
    const float* W2   = (const float*)d_in[6];
    const float* g2   = (const float*)d_in[8];
    const float* be2  = (const float*)d_in[9];
    const float* W3   = (const float*)d_in[10];
    const float* g3   = (const float*)d_in[12];
    const float* be3  = (const float*)d_in[13];

    float* out     = (float*)d_out;
    float* sampled = out;
    float* qz      = out + (size_t)BB * CC * TT;

    float* zbuf  = symf(g_z);
    float* ybuf  = symf(g_y);
    float* s1    = symf(g_s1);
    float* s2    = symf(g_s2);
    float* ql    = symf(g_ql);
    float* meanb = symf(g_mean);
    float* denb  = symf(g_denom);
    float* dstat = symf(g_dstat);

    zero_z_kernel<<<(BB * CC + 255) / 256, 256>>>(zbuf);

    bool first = true;
    for (int t = 0; t < TT - 1; ++t) {
        int L = t + 1;
        gemm128x64_kernel<<<dim3(8 * L, C2 / 128), 256>>>(W1, x, zbuf, ybuf, C2, C2, L, 0);
        bnstats_launch(ybuf, C2, L, meanb, denb);
        if (first) {
            // Diagnostic: full-scale layer-3 coalesced bnstats as an early
            // launch so the ncu single-launch capture lands on it.
            bnstats_coal<16><<<CKK / 8, 256>>>(ybuf, CKK, dstat, dstat + CKK);
            first = false;
        }
        lif_kernel<<<(BB * C2) / 256, 256>>>(ybuf, meanb, denb, g1, be1, C2, L, s1, 0);

        gemm128x64_kernel<<<dim3(8 * L, C4 / 128), 256>>>(W2, s1, nullptr, ybuf, C4, C2, L, 1);
        bnstats_launch(ybuf, C4, L, meanb, denb);
        lif_kernel<<<(BB * C4) / 256, 256>>>(ybuf, meanb, denb, g2, be2, C4, L, s2, 0);

        gemm128x64_kernel<<<dim3(8 * L, CKK / 128), 256>>>(W3, s2, nullptr, ybuf, CKK, C4, L, 1);
        bnstats_launch(ybuf, CKK, L, meanb, denb);
        lif_kernel<<<(BB * CKK) / 256, 256>>>(ybuf, meanb, denb, g3, be3, CKK, L, ql, 1);
        gather_z_kernel<<<(BB * CC + 255) / 256, 256>>>(ql, ridx, zbuf, t);
    }

    {
        int L = TT;
        gemm128x64_kernel<<<dim3(8 * L, C2 / 128), 256>>>(W1, x, zbuf, ybuf, C2, C2, L, 0);
        bnstats_launch(ybuf, C2, L, meanb, denb);
        lif_kernel<<<(BB * C2) / 256, 256>>>(ybuf, meanb, denb, g1, be1, C2, L, s1, 0);

        gemm128x64_kernel<<<dim3(8 * L, C4 / 128), 256>>>(W2, s1, nullptr, ybuf, C4, C2, L, 1);
        bnstats_launch(ybuf, C4, L, meanb, denb);
        lif_kernel<<<(BB * C4) / 256, 256>>>(ybuf, meanb, denb, g2, be2, C4, L, s2, 0);

        gemm128x64_kernel<<<dim3(8 * L, CKK / 128), 256>>>(W3, s2, nullptr, ybuf, CKK, C4, L, 1);
        bnstats_launch(ybuf, CKK, L, meanb, denb);
        lif_kernel<<<(BB * CKK) / 256, 256>>>(ybuf, meanb, denb, g3, be3, CKK, L, qz, 0);
    }

    gather_sampled_kernel<<<(BB * CC * TT) / 256, 256>>>(qz, ridx, sampled);
}